// round 4
// baseline (speedup 1.0000x reference)
#include <cuda_runtime.h>
#include <cuda_bf16.h>

// Problem constants (fixed by the dataset)
#define BB 16
#define NN 16384
#define DD 128
#define EE 65536
#define NODES (BB * NN)          // 262144
#define LN_EPS 1e-5f

// ---------------- scratch (__device__ globals: no allocation allowed) ----------
__device__ int    g_is32;           // 1 => edge buffer is int32, 0 => int64
__device__ int    g_deg[NN];
__device__ int    g_rowptr[NN + 1];
__device__ int    g_cursor[NN];
__device__ int    g_csr[EE];
// float4 type => guaranteed 16-byte alignment for .128 accesses
__device__ float4 g_neigh[(size_t)NODES * (DD / 4)];   // 128 MB scratch

__device__ __forceinline__ int clampN(int v) {
    return v < 0 ? 0 : (v >= NN ? NN - 1 : v);
}

__device__ __forceinline__ int edge_src(const int* e32, int e) {
    return clampN(g_is32 ? e32[e] : e32[2 * e]);
}
__device__ __forceinline__ int edge_dst(const int* e32, int e) {
    return clampN(g_is32 ? e32[EE + e] : e32[2 * EE + 2 * e]);
}

// ---------------- dtype detect + CSR build -------------------------------------
__global__ void k_zero_deg() {
    int i = blockIdx.x * blockDim.x + threadIdx.x;
    if (i < NN) g_deg[i] = 0;
    if (i == 0) g_is32 = 0;
}

// If data were int64 (values < 2^31), every odd 32-bit word of the first EE
// entries would be 0. Any nonzero odd word => int32 layout.
__global__ void k_detect(const int* __restrict__ e32) {
    int i = blockIdx.x * blockDim.x + threadIdx.x;
    if (i < EE && e32[2 * i + 1] != 0) g_is32 = 1;
}

__global__ void k_count(const int* __restrict__ e32) {
    int e = blockIdx.x * blockDim.x + threadIdx.x;
    if (e < EE) atomicAdd(&g_deg[edge_dst(e32, e)], 1);
}

// single block, 1024 threads, 16 elements each
__global__ void k_scan() {
    __shared__ int sums[1024];
    int t = threadIdx.x;
    int base = t * 16;
    int local[16];
    int s = 0;
#pragma unroll
    for (int m = 0; m < 16; m++) { local[m] = g_deg[base + m]; s += local[m]; }
    sums[t] = s;
    __syncthreads();
    for (int off = 1; off < 1024; off <<= 1) {
        int v = (t >= off) ? sums[t - off] : 0;
        __syncthreads();
        sums[t] += v;
        __syncthreads();
    }
    int run = sums[t] - s;   // exclusive prefix
#pragma unroll
    for (int m = 0; m < 16; m++) {
        g_rowptr[base + m] = run;
        g_cursor[base + m] = run;
        run += local[m];
    }
    if (t == 1023) g_rowptr[NN] = run;
}

__global__ void k_fill(const int* __restrict__ e32) {
    int e = blockIdx.x * blockDim.x + threadIdx.x;
    if (e < EE) {
        int d = edge_dst(e32, e);
        int pos = atomicAdd(&g_cursor[d], 1);
        if (pos >= 0 && pos < EE) g_csr[pos] = edge_src(e32, e);
    }
}

// ---------------- neighbor mean aggregation ------------------------------------
// one warp per (batch, node); lane handles 4 feature dims (float4)
__global__ void k_agg(const float* __restrict__ x) {
    int t = blockIdx.x * blockDim.x + threadIdx.x;
    int w = t >> 5;           // warp id in [0, NODES)
    int lane = t & 31;
    int b = w >> 14;          // / NN
    int n = w & (NN - 1);
    int s0 = g_rowptr[n];
    int s1 = g_rowptr[n + 1];
    const float4* xb = (const float4*)x + (size_t)b * NN * (DD / 4);
    float ax = 0.f, ay = 0.f, az = 0.f, aw = 0.f;
    for (int e = s0; e < s1; e++) {
        float4 v = xb[(size_t)g_csr[e] * (DD / 4) + lane];
        ax += v.x; ay += v.y; az += v.z; aw += v.w;
    }
    int d = s1 - s0;
    float inv = 1.0f / (float)(d > 0 ? d : 1);
    float4 r;
    r.x = ax * inv; r.y = ay * inv; r.z = az * inv; r.w = aw * inv;
    g_neigh[(size_t)w * (DD / 4) + lane] = r;
}

// ---------------- fused dual-GEMM + bias + LayerNorm + ReLU --------------------
// Tile: 64 rows (nodes) x 128 cols. 256 threads = 8 warps.
// Warp `it` owns rows it*8..it*8+7; lane jt owns cols {jt, jt+32, jt+64, jt+96}.
// Weights in smem with row stride 129 (odd) => scalar LDS bank = (jt + k) % 32,
// conflict-free. x/neigh tile reads are warp-broadcast LDS.128.
#define WSTR 129
#define SMEM_FLOATS (2 * DD * WSTR + 2 * 64 * DD)

__global__ void __launch_bounds__(256, 1)
k_gemm(const float* __restrict__ x,
       const float* __restrict__ Wself,
       const float* __restrict__ Wneigh,
       const float* __restrict__ bias,
       const float* __restrict__ gamma,
       const float* __restrict__ beta,
       float* __restrict__ out) {
    extern __shared__ float smem[];
    float* ws = smem;                 // [128][129]
    float* wn = ws + DD * WSTR;       // [128][129]
    float* xs = wn + DD * WSTR;       // [64][128]
    float* ns = xs + 64 * DD;         // [64][128]

    int tid = threadIdx.x;

    // load weights (row-major, padded stride). float4 global loads, scalar STS
    const float4* ws4 = (const float4*)Wself;
    const float4* wn4 = (const float4*)Wneigh;
#pragma unroll
    for (int r = 0; r < 16; r++) {
        int f4 = tid + 256 * r;             // float4 index in [0, 4096)
        int j = f4 >> 5;
        int k4 = f4 & 31;
        float4 v = ws4[f4];
        float* p = &ws[j * WSTR + 4 * k4];
        p[0] = v.x; p[1] = v.y; p[2] = v.z; p[3] = v.w;
        v = wn4[f4];
        p = &wn[j * WSTR + 4 * k4];
        p[0] = v.x; p[1] = v.y; p[2] = v.z; p[3] = v.w;
    }

    // load x / neigh tiles (contiguous rows)
    size_t g0 = (size_t)blockIdx.x * 64;
    const float4* xsrc = (const float4*)(x + g0 * DD);
    const float4* nsrc = g_neigh + g0 * (DD / 4);
    float4* xs4 = (float4*)xs;
    float4* ns4 = (float4*)ns;
#pragma unroll
    for (int r = 0; r < 8; r++) {
        int i4 = tid + 256 * r;             // in [0, 2048)
        xs4[i4] = xsrc[i4];
        ns4[i4] = nsrc[i4];
    }
    __syncthreads();

    int it = tid >> 5;
    int jt = tid & 31;

    float bv[4], gv[4], btv[4];
#pragma unroll
    for (int jj = 0; jj < 4; jj++) {
        int j = jt + 32 * jj;
        bv[jj] = bias[j];
        gv[jj] = gamma[j];
        btv[jj] = beta[j];
    }

    float acc[8][4];
#pragma unroll
    for (int ii = 0; ii < 8; ii++)
#pragma unroll
        for (int jj = 0; jj < 4; jj++) acc[ii][jj] = bv[jj];

    for (int k0 = 0; k0 < DD; k0 += 4) {
        float4 xr[8], nr[8];
#pragma unroll
        for (int ii = 0; ii < 8; ii++) {
            xr[ii] = *(const float4*)&xs[(it * 8 + ii) * DD + k0];
            nr[ii] = *(const float4*)&ns[(it * 8 + ii) * DD + k0];
        }
#pragma unroll
        for (int kk = 0; kk < 4; kk++) {
            float wsv[4], wnv[4];
#pragma unroll
            for (int jj = 0; jj < 4; jj++) {
                wsv[jj] = ws[(jt + 32 * jj) * WSTR + k0 + kk];
                wnv[jj] = wn[(jt + 32 * jj) * WSTR + k0 + kk];
            }
#pragma unroll
            for (int ii = 0; ii < 8; ii++) {
                float xv = ((const float*)&xr[ii])[kk];
                float nv = ((const float*)&nr[ii])[kk];
#pragma unroll
                for (int jj = 0; jj < 4; jj++) {
                    acc[ii][jj] = fmaf(xv, wsv[jj], fmaf(nv, wnv[jj], acc[ii][jj]));
                }
            }
        }
    }

    // LayerNorm + ReLU + store (warp owns full 128-wide row)
#pragma unroll
    for (int ii = 0; ii < 8; ii++) {
        float s = 0.f, ss = 0.f;
#pragma unroll
        for (int jj = 0; jj < 4; jj++) {
            s += acc[ii][jj];
            ss += acc[ii][jj] * acc[ii][jj];
        }
#pragma unroll
        for (int off = 16; off > 0; off >>= 1) {
            s  += __shfl_xor_sync(0xFFFFFFFFu, s,  off);
            ss += __shfl_xor_sync(0xFFFFFFFFu, ss, off);
        }
        float mean = s * (1.0f / DD);
        float var = ss * (1.0f / DD) - mean * mean;
        float rstd = rsqrtf(var + LN_EPS);
        size_t row = g0 + it * 8 + ii;
        float* orow = out + row * DD;
#pragma unroll
        for (int jj = 0; jj < 4; jj++) {
            float v = (acc[ii][jj] - mean) * rstd * gv[jj] + btv[jj];
            orow[jt + 32 * jj] = v > 0.f ? v : 0.f;
        }
    }
}

// ---------------- launch -------------------------------------------------------
extern "C" void kernel_launch(void* const* d_in, const int* in_sizes, int n_in,
                              void* d_out, int out_size) {
    const float* x = nullptr;
    const int* edge = nullptr;
    const float* Wself = nullptr;
    const float* Wneigh = nullptr;
    const float* bias = nullptr;
    const float* gamma = nullptr;
    const float* beta = nullptr;
    int nW = 0, nV = 0;
    for (int i = 0; i < n_in; i++) {
        int s = in_sizes[i];
        if (s == NODES * DD) {
            if (!x) x = (const float*)d_in[i];
        } else if (s == 2 * EE || s == 4 * EE) {
            edge = (const int*)d_in[i];
        } else if (s == DD * DD) {
            if (nW == 0) Wself = (const float*)d_in[i];
            else if (nW == 1) Wneigh = (const float*)d_in[i];
            nW++;
        } else if (s == DD) {
            if (nV == 0) bias = (const float*)d_in[i];
            else if (nV == 1) gamma = (const float*)d_in[i];
            else if (nV == 2) beta = (const float*)d_in[i];
            nV++;
        }
    }

    cudaFuncSetAttribute(k_gemm, cudaFuncAttributeMaxDynamicSharedMemorySize,
                         SMEM_FLOATS * (int)sizeof(float));

    k_zero_deg<<<(NN + 255) / 256, 256>>>();
    k_detect<<<EE / 256, 256>>>(edge);
    k_count<<<EE / 256, 256>>>(edge);
    k_scan<<<1, 1024>>>();
    k_fill<<<EE / 256, 256>>>(edge);
    k_agg<<<(NODES * 32) / 256, 256>>>(x);
    k_gemm<<<NODES / 64, 256, SMEM_FLOATS * (int)sizeof(float)>>>(
        x, Wself, Wneigh, bias, gamma, beta, (float*)d_out);
}

// round 6
// speedup vs baseline: 1.0783x; 1.0783x over previous
#include <cuda_runtime.h>
#include <cuda_bf16.h>
#include <mma.h>
#include <cstdint>

using namespace nvcuda;

// Problem constants (fixed by the dataset)
#define BB 16
#define NN 16384
#define DD 128
#define EE 65536
#define NODES (BB * NN)          // 262144
#define LN_EPS 1e-5f

// ================= scratch (__device__ globals) ================================
__device__ int g_is32;
__device__ __align__(16) int g_deg[NN];
__device__ __align__(16) int g_rowptr[NN + 1];
__device__ __align__(16) int g_cursor[NN];
__device__ int g_csr[EE];
__device__ uint4 g_nh4[(size_t)NODES * 16];   // neigh hi, bf16 rows (256B each)
__device__ uint4 g_nl4[(size_t)NODES * 16];   // neigh lo
__device__ uint4 g_wall4[4 * 2048];           // Wsh | Wsl | Wnh | Wnl (bf16, row-major)

__device__ __forceinline__ int clampN(int v) {
    return v < 0 ? 0 : (v >= NN ? NN - 1 : v);
}
__device__ __forceinline__ int edge_src(const int* e32, int e) {
    return clampN(g_is32 ? e32[e] : e32[2 * e]);
}
__device__ __forceinline__ int edge_dst(const int* e32, int e) {
    return clampN(g_is32 ? e32[EE + e] : e32[2 * EE + 2 * e]);
}
__device__ __forceinline__ uint32_t bfpair(__nv_bfloat16 a, __nv_bfloat16 b) {
    __nv_bfloat162 t(a, b);
    return *reinterpret_cast<uint32_t*>(&t);
}
__device__ __forceinline__ uint32_t packbf(float a, float b) {
    return bfpair(__float2bfloat16(a), __float2bfloat16(b));
}

// ================= CSR build ===================================================
__global__ void k_zero_deg() {
    int i = blockIdx.x * blockDim.x + threadIdx.x;
    if (i < NN) g_deg[i] = 0;
    if (i == 0) g_is32 = 0;
}
__global__ void k_detect(const int* __restrict__ e32) {
    int i = blockIdx.x * blockDim.x + threadIdx.x;
    if (i < EE && e32[2 * i + 1] != 0) g_is32 = 1;
}
__global__ void k_count(const int* __restrict__ e32) {
    int e = blockIdx.x * blockDim.x + threadIdx.x;
    if (e < EE) atomicAdd(&g_deg[edge_dst(e32, e)], 1);
}

// vectorized single-block scan: 1024 threads x 16 elems, warp shuffles
__global__ void k_scan() {
    __shared__ int wsum[32], wpre[32];
    int t = threadIdx.x, lane = t & 31, w = t >> 5;
    const int4* dg = (const int4*)g_deg;
    int loc[16];
#pragma unroll
    for (int q = 0; q < 4; q++) {
        int4 v = dg[t * 4 + q];
        loc[4 * q + 0] = v.x; loc[4 * q + 1] = v.y;
        loc[4 * q + 2] = v.z; loc[4 * q + 3] = v.w;
    }
    int s = 0;
#pragma unroll
    for (int m = 0; m < 16; m++) s += loc[m];
    int inc = s;
#pragma unroll
    for (int o = 1; o < 32; o <<= 1) {
        int u = __shfl_up_sync(0xFFFFFFFFu, inc, o);
        if (lane >= o) inc += u;
    }
    if (lane == 31) wsum[w] = inc;
    __syncthreads();
    if (w == 0) {
        int a = wsum[lane], ai = a;
#pragma unroll
        for (int o = 1; o < 32; o <<= 1) {
            int u = __shfl_up_sync(0xFFFFFFFFu, ai, o);
            if (lane >= o) ai += u;
        }
        wpre[lane] = ai - a;
    }
    __syncthreads();
    int run = wpre[w] + (inc - s);
    int rp[16];
#pragma unroll
    for (int m = 0; m < 16; m++) { rp[m] = run; run += loc[m]; }
    int4* rpo = (int4*)g_rowptr;
    int4* cu = (int4*)g_cursor;
#pragma unroll
    for (int q = 0; q < 4; q++) {
        int4 o4 = make_int4(rp[4 * q], rp[4 * q + 1], rp[4 * q + 2], rp[4 * q + 3]);
        rpo[t * 4 + q] = o4;
        cu[t * 4 + q] = o4;
    }
    if (t == 1023) g_rowptr[NN] = run;
}

__global__ void k_fill(const int* __restrict__ e32) {
    int e = blockIdx.x * blockDim.x + threadIdx.x;
    if (e < EE) {
        int d = edge_dst(e32, e);
        int pos = atomicAdd(&g_cursor[d], 1);
        if (pos >= 0 && pos < EE) g_csr[pos] = edge_src(e32, e);
    }
}

// ================= weight split: fp32 -> bf16 hi/lo ============================
__global__ void k_convert_w(const float* __restrict__ Ws, const float* __restrict__ Wn) {
    int i = blockIdx.x * blockDim.x + threadIdx.x;
    if (i < DD * DD) {
        __nv_bfloat16* b = (__nv_bfloat16*)g_wall4;
        float a = Ws[i];
        __nv_bfloat16 h = __float2bfloat16(a);
        b[i] = h;
        b[16384 + i] = __float2bfloat16(a - __bfloat162float(h));
        a = Wn[i];
        h = __float2bfloat16(a);
        b[32768 + i] = h;
        b[49152 + i] = __float2bfloat16(a - __bfloat162float(h));
    }
}

// ================= neighbor mean aggregation (writes bf16 hi/lo) ===============
__global__ void k_agg(const float* __restrict__ x) {
    int t = blockIdx.x * blockDim.x + threadIdx.x;
    int w = t >> 5;           // (batch,node) id in [0, NODES)
    int lane = t & 31;
    int b = w >> 14;
    int n = w & (NN - 1);
    int s0 = g_rowptr[n];
    int s1 = g_rowptr[n + 1];
    const float4* xb = (const float4*)x + (size_t)b * NN * 32;
    float ax = 0.f, ay = 0.f, az = 0.f, aw = 0.f;
    for (int e = s0; e < s1; e++) {
        float4 v = xb[(size_t)g_csr[e] * 32 + lane];
        ax += v.x; ay += v.y; az += v.z; aw += v.w;
    }
    int d = s1 - s0;
    float inv = 1.0f / (float)(d > 0 ? d : 1);
    ax *= inv; ay *= inv; az *= inv; aw *= inv;
    __nv_bfloat16 hx = __float2bfloat16(ax), hy = __float2bfloat16(ay);
    __nv_bfloat16 hz = __float2bfloat16(az), hw = __float2bfloat16(aw);
    uint2 hi = make_uint2(bfpair(hx, hy), bfpair(hz, hw));
    uint2 lo = make_uint2(packbf(ax - __bfloat162float(hx), ay - __bfloat162float(hy)),
                          packbf(az - __bfloat162float(hz), aw - __bfloat162float(hw)));
    ((uint2*)g_nh4)[(size_t)w * 32 + lane] = hi;
    ((uint2*)g_nl4)[(size_t)w * 32 + lane] = lo;
}

// ================= WMMA bf16 GEMM + bias + LayerNorm + ReLU ====================
// CTA = 128 rows x 128 cols, 256 threads = 8 warps (warp tile 32x64).
// A tiles in smem (ld=136): xh, xl, nh, nl (x split fused into the tile load).
// B = 4 weight tiles double-buffered; pass order reuses Wsh and Wnh:
//   [B=Wsh: xh, xl] [B=Wsl: xh] [B=Wnh: nh, nl] [B=Wnl: nh]
#define LDA 136
#define ATILE (128 * LDA * 2)                // 34816 bytes
#define SM_BIAS  0
#define SM_GAMMA 512
#define SM_BETA  1024
#define SM_A     2048
#define A_XH (SM_A + 0 * ATILE)
#define A_XL (SM_A + 1 * ATILE)
#define A_NH (SM_A + 2 * ATILE)
#define A_NL (SM_A + 3 * ATILE)
#define SM_B0 (SM_A + 4 * ATILE)
#define SM_B1 (SM_B0 + ATILE)
#define SMEM_TOTAL (SM_B1 + ATILE)           // 210944 bytes
#define SM_F  SM_A                            // fp32 out buffer (reuses xh/xl)

__global__ void __launch_bounds__(256, 1)
k_mm(const float* __restrict__ x,
     const float* __restrict__ bias,
     const float* __restrict__ gamma,
     const float* __restrict__ beta,
     float* __restrict__ out) {
    extern __shared__ char smem[];
    int tid = threadIdx.x;
    int wid = tid >> 5;

    if (tid < DD) {
        ((float*)(smem + SM_BIAS))[tid] = bias[tid];
        ((float*)(smem + SM_GAMMA))[tid] = gamma[tid];
        ((float*)(smem + SM_BETA))[tid] = beta[tid];
    }

    size_t g0 = (size_t)blockIdx.x * 128;
    int m = tid >> 1;             // row 0..127 (2 threads per row)
    int half = tid & 1;           // 64-element half

    // ---- A fill: x -> bf16 hi/lo split (fused), neigh hi/lo copy --------------
    {
        const uint4* xs = (const uint4*)x + (g0 + m) * 32 + half * 16;
        uint4 hi[8], lo[8];
#pragma unroll
        for (int i = 0; i < 16; i++) {
            uint4 u = xs[i];
            float f0 = __uint_as_float(u.x), f1 = __uint_as_float(u.y);
            float f2 = __uint_as_float(u.z), f3 = __uint_as_float(u.w);
            __nv_bfloat16 h0 = __float2bfloat16(f0), h1 = __float2bfloat16(f1);
            __nv_bfloat16 h2 = __float2bfloat16(f2), h3 = __float2bfloat16(f3);
            ((uint32_t*)hi)[2 * i] = bfpair(h0, h1);
            ((uint32_t*)hi)[2 * i + 1] = bfpair(h2, h3);
            ((uint32_t*)lo)[2 * i] = packbf(f0 - __bfloat162float(h0), f1 - __bfloat162float(h1));
            ((uint32_t*)lo)[2 * i + 1] = packbf(f2 - __bfloat162float(h2), f3 - __bfloat162float(h3));
        }
        uint4* dh = (uint4*)(smem + A_XH + m * (LDA * 2) + half * 128);
        uint4* dl = (uint4*)(smem + A_XL + m * (LDA * 2) + half * 128);
#pragma unroll
        for (int i = 0; i < 8; i++) { dh[i] = hi[i]; dl[i] = lo[i]; }

        const uint4* nh = g_nh4 + (g0 + m) * 16 + half * 8;
        const uint4* nl = g_nl4 + (g0 + m) * 16 + half * 8;
        uint4* dnh = (uint4*)(smem + A_NH + m * (LDA * 2) + half * 128);
        uint4* dnl = (uint4*)(smem + A_NL + m * (LDA * 2) + half * 128);
#pragma unroll
        for (int i = 0; i < 8; i++) { dnh[i] = nh[i]; dnl[i] = nl[i]; }
    }

    // ---- B staging helpers ----------------------------------------------------
    uint4 breg[8];
    const uint4* wsrc = g_wall4 + m * 16 + half * 8;
#define LDG_B(tile)  do { const uint4* _s = wsrc + (tile) * 2048;                \
        _Pragma("unroll") for (int i = 0; i < 8; i++) breg[i] = _s[i]; } while (0)
#define STS_B(buf)   do { uint4* _d = (uint4*)(smem + (buf) + m * (LDA * 2) + half * 128); \
        _Pragma("unroll") for (int i = 0; i < 8; i++) _d[i] = breg[i]; } while (0)

    LDG_B(0);
    STS_B(SM_B0);
    __syncthreads();

    // ---- WMMA passes ----------------------------------------------------------
    int wm = wid & 3, wn = wid >> 2;
    int row0 = wm * 32, col0 = wn * 64;

    wmma::fragment<wmma::accumulator, 16, 16, 16, float> fc[2][4];
#pragma unroll
    for (int i = 0; i < 2; i++)
#pragma unroll
        for (int j = 0; j < 4; j++) wmma::fill_fragment(fc[i][j], 0.0f);

#define DO_PASS(AOFF, BOFF) do {                                                  \
    const __nv_bfloat16* _ab = (const __nv_bfloat16*)(smem + (AOFF));             \
    const __nv_bfloat16* _bb = (const __nv_bfloat16*)(smem + (BOFF));             \
    _Pragma("unroll")                                                             \
    for (int kk = 0; kk < 8; kk++) {                                              \
        wmma::fragment<wmma::matrix_a, 16, 16, 16, __nv_bfloat16, wmma::row_major> fa[2]; \
        wmma::fragment<wmma::matrix_b, 16, 16, 16, __nv_bfloat16, wmma::col_major> fb[4]; \
        wmma::load_matrix_sync(fa[0], _ab + (row0 + 0) * LDA + kk * 16, LDA);     \
        wmma::load_matrix_sync(fa[1], _ab + (row0 + 16) * LDA + kk * 16, LDA);    \
        _Pragma("unroll")                                                         \
        for (int j = 0; j < 4; j++)                                               \
            wmma::load_matrix_sync(fb[j], _bb + (col0 + 16 * j) * LDA + kk * 16, LDA); \
        _Pragma("unroll")                                                         \
        for (int i = 0; i < 2; i++)                                               \
            _Pragma("unroll")                                                     \
            for (int j = 0; j < 4; j++)                                           \
                wmma::mma_sync(fc[i][j], fa[i], fb[j], fc[i][j]);                 \
    }                                                                             \
} while (0)

    LDG_B(1);                     // prefetch Wsl
    DO_PASS(A_XH, SM_B0);
    DO_PASS(A_XL, SM_B0);
    __syncthreads();
    STS_B(SM_B1);
    __syncthreads();

    LDG_B(2);                     // prefetch Wnh
    DO_PASS(A_XH, SM_B1);
    __syncthreads();
    STS_B(SM_B0);
    __syncthreads();

    LDG_B(3);                     // prefetch Wnl
    DO_PASS(A_NH, SM_B0);
    DO_PASS(A_NL, SM_B0);
    __syncthreads();
    STS_B(SM_B1);
    __syncthreads();

    DO_PASS(A_NH, SM_B1);

    // ---- store accum to smem fp32 (reuses xh/xl space; passes 0-2 done) -------
    float* fsm = (float*)(smem + SM_F);
#pragma unroll
    for (int i = 0; i < 2; i++)
#pragma unroll
        for (int j = 0; j < 4; j++)
            wmma::store_matrix_sync(fsm + (row0 + 16 * i) * 128 + col0 + 16 * j,
                                    fc[i][j], 128, wmma::mem_row_major);
    __syncthreads();

    // ---- bias + LayerNorm + ReLU + store --------------------------------------
    {
        const float* src = fsm + m * 128 + half * 64;
        const float* bs = (const float*)(smem + SM_BIAS) + half * 64;
        float v[64];
        float s = 0.f, ss = 0.f;
#pragma unroll
        for (int c = 0; c < 64; c++) {
            float t = src[c] + bs[c];
            v[c] = t;
            s += t;
            ss += t * t;
        }
        // partner (tid^1) holds the other half of this row — same warp
        s  += __shfl_xor_sync(0xFFFFFFFFu, s, 1);
        ss += __shfl_xor_sync(0xFFFFFFFFu, ss, 1);
        float mean = s * (1.0f / DD);
        float var = ss * (1.0f / DD) - mean * mean;
        float rstd = rsqrtf(var + LN_EPS);
        const float* gs = (const float*)(smem + SM_GAMMA) + half * 64;
        const float* bt = (const float*)(smem + SM_BETA) + half * 64;
        float4* orow = (float4*)(out + (g0 + m) * DD + half * 64);
#pragma unroll
        for (int c4 = 0; c4 < 16; c4++) {
            float v0 = (v[4 * c4 + 0] - mean) * rstd * gs[4 * c4 + 0] + bt[4 * c4 + 0];
            float v1 = (v[4 * c4 + 1] - mean) * rstd * gs[4 * c4 + 1] + bt[4 * c4 + 1];
            float v2 = (v[4 * c4 + 2] - mean) * rstd * gs[4 * c4 + 2] + bt[4 * c4 + 2];
            float v3 = (v[4 * c4 + 3] - mean) * rstd * gs[4 * c4 + 3] + bt[4 * c4 + 3];
            float4 ov;
            ov.x = v0 > 0.f ? v0 : 0.f;
            ov.y = v1 > 0.f ? v1 : 0.f;
            ov.z = v2 > 0.f ? v2 : 0.f;
            ov.w = v3 > 0.f ? v3 : 0.f;
            orow[c4] = ov;
        }
    }
}

// ================= launch ======================================================
extern "C" void kernel_launch(void* const* d_in, const int* in_sizes, int n_in,
                              void* d_out, int out_size) {
    const float* x = nullptr;
    const int* edge = nullptr;
    const float* Wself = nullptr;
    const float* Wneigh = nullptr;
    const float* bias = nullptr;
    const float* gamma = nullptr;
    const float* beta = nullptr;
    int nW = 0, nV = 0;
    for (int i = 0; i < n_in; i++) {
        int s = in_sizes[i];
        if (s == NODES * DD) {
            if (!x) x = (const float*)d_in[i];
        } else if (s == 2 * EE || s == 4 * EE) {
            edge = (const int*)d_in[i];
        } else if (s == DD * DD) {
            if (nW == 0) Wself = (const float*)d_in[i];
            else if (nW == 1) Wneigh = (const float*)d_in[i];
            nW++;
        } else if (s == DD) {
            if (nV == 0) bias = (const float*)d_in[i];
            else if (nV == 1) gamma = (const float*)d_in[i];
            else if (nV == 2) beta = (const float*)d_in[i];
            nV++;
        }
    }

    cudaFuncSetAttribute(k_mm, cudaFuncAttributeMaxDynamicSharedMemorySize, SMEM_TOTAL);

    k_zero_deg<<<(NN + 255) / 256, 256>>>();
    k_detect<<<EE / 256, 256>>>(edge);
    k_count<<<EE / 256, 256>>>(edge);
    k_scan<<<1, 1024>>>();
    k_fill<<<EE / 256, 256>>>(edge);
    k_convert_w<<<(DD * DD + 255) / 256, 256>>>(Wself, Wneigh);
    k_agg<<<(NODES * 32) / 256, 256>>>(x);
    k_mm<<<NODES / 128, 256, SMEM_TOTAL>>>(x, bias, gamma, beta, (float*)d_out);
}

// round 7
// speedup vs baseline: 1.0908x; 1.0116x over previous
#include <cuda_runtime.h>
#include <cuda_bf16.h>
#include <mma.h>
#include <cstdint>

using namespace nvcuda;

// Problem constants (fixed by the dataset)
#define BB 16
#define NN 16384
#define DD 128
#define EE 65536
#define NODES (BB * NN)          // 262144
#define LN_EPS 1e-5f

// ================= scratch (__device__ globals) ================================
__device__ int g_is32;
__device__ __align__(16) int g_deg[NN];
__device__ __align__(16) int g_rowptr[NN + 1];
__device__ __align__(16) int g_cursor[NN];
__device__ int g_csr[EE];
__device__ uint4 g_nh4[(size_t)NODES * 16];   // neigh hi, bf16 rows (256B each)
__device__ uint4 g_nl4[(size_t)NODES * 16];   // neigh lo
__device__ uint4 g_wall4[4 * 2048];           // Wsh | Wsl | Wnh | Wnl (bf16, row-major)

__device__ __forceinline__ int clampN(int v) {
    return v < 0 ? 0 : (v >= NN ? NN - 1 : v);
}
__device__ __forceinline__ int edge_src(const int* e32, int e) {
    return clampN(g_is32 ? e32[e] : e32[2 * e]);
}
__device__ __forceinline__ int edge_dst(const int* e32, int e) {
    return clampN(g_is32 ? e32[EE + e] : e32[2 * EE + 2 * e]);
}
__device__ __forceinline__ uint32_t bfpair(__nv_bfloat16 a, __nv_bfloat16 b) {
    __nv_bfloat162 t(a, b);
    return *reinterpret_cast<uint32_t*>(&t);
}
__device__ __forceinline__ uint32_t packbf(float a, float b) {
    return bfpair(__float2bfloat16(a), __float2bfloat16(b));
}

// ================= fused init: zero degrees + dtype detect + weight split ======
// 65536 threads; independent index ranges, no cross-dependencies.
__global__ void k_init(const int* __restrict__ e32,
                       const float* __restrict__ Ws, const float* __restrict__ Wn) {
    int i = blockIdx.x * blockDim.x + threadIdx.x;
    if (i == 0) g_is32 = 0;
    if (i < NN) g_deg[i] = 0;
    // detect: if edge buffer were int64 (<2^31 values), odd words are all 0
    if (i < EE && e32[2 * i + 1] != 0) g_is32 = 1;
    if (i < DD * DD) {
        __nv_bfloat16* b = (__nv_bfloat16*)g_wall4;
        float a = Ws[i];
        __nv_bfloat16 h = __float2bfloat16(a);
        b[i] = h;
        b[16384 + i] = __float2bfloat16(a - __bfloat162float(h));
        a = Wn[i];
        h = __float2bfloat16(a);
        b[32768 + i] = h;
        b[49152 + i] = __float2bfloat16(a - __bfloat162float(h));
    }
}

__global__ void k_count(const int* __restrict__ e32) {
    int e = blockIdx.x * blockDim.x + threadIdx.x;
    if (e < EE) atomicAdd(&g_deg[edge_dst(e32, e)], 1);
}

// vectorized single-block scan: 1024 threads x 16 elems, warp shuffles
__global__ void k_scan() {
    __shared__ int wsum[32], wpre[32];
    int t = threadIdx.x, lane = t & 31, w = t >> 5;
    const int4* dg = (const int4*)g_deg;
    int loc[16];
#pragma unroll
    for (int q = 0; q < 4; q++) {
        int4 v = dg[t * 4 + q];
        loc[4 * q + 0] = v.x; loc[4 * q + 1] = v.y;
        loc[4 * q + 2] = v.z; loc[4 * q + 3] = v.w;
    }
    int s = 0;
#pragma unroll
    for (int m = 0; m < 16; m++) s += loc[m];
    int inc = s;
#pragma unroll
    for (int o = 1; o < 32; o <<= 1) {
        int u = __shfl_up_sync(0xFFFFFFFFu, inc, o);
        if (lane >= o) inc += u;
    }
    if (lane == 31) wsum[w] = inc;
    __syncthreads();
    if (w == 0) {
        int a = wsum[lane], ai = a;
#pragma unroll
        for (int o = 1; o < 32; o <<= 1) {
            int u = __shfl_up_sync(0xFFFFFFFFu, ai, o);
            if (lane >= o) ai += u;
        }
        wpre[lane] = ai - a;
    }
    __syncthreads();
    int run = wpre[w] + (inc - s);
    int rp[16];
#pragma unroll
    for (int m = 0; m < 16; m++) { rp[m] = run; run += loc[m]; }
    int4* rpo = (int4*)g_rowptr;
    int4* cu = (int4*)g_cursor;
#pragma unroll
    for (int q = 0; q < 4; q++) {
        int4 o4 = make_int4(rp[4 * q], rp[4 * q + 1], rp[4 * q + 2], rp[4 * q + 3]);
        rpo[t * 4 + q] = o4;
        cu[t * 4 + q] = o4;
    }
    if (t == 1023) g_rowptr[NN] = run;
}

__global__ void k_fill(const int* __restrict__ e32) {
    int e = blockIdx.x * blockDim.x + threadIdx.x;
    if (e < EE) {
        int d = edge_dst(e32, e);
        int pos = atomicAdd(&g_cursor[d], 1);
        if (pos >= 0 && pos < EE) g_csr[pos] = edge_src(e32, e);
    }
}

// ================= neighbor mean aggregation (writes bf16 hi/lo) ===============
__global__ void k_agg(const float* __restrict__ x) {
    int t = blockIdx.x * blockDim.x + threadIdx.x;
    int w = t >> 5;           // (batch,node) id in [0, NODES)
    int lane = t & 31;
    int b = w >> 14;
    int n = w & (NN - 1);
    int s0 = g_rowptr[n];
    int s1 = g_rowptr[n + 1];
    const float4* xb = (const float4*)x + (size_t)b * NN * 32;
    float ax = 0.f, ay = 0.f, az = 0.f, aw = 0.f;
    for (int e = s0; e < s1; e++) {
        float4 v = xb[(size_t)g_csr[e] * 32 + lane];
        ax += v.x; ay += v.y; az += v.z; aw += v.w;
    }
    int d = s1 - s0;
    float inv = 1.0f / (float)(d > 0 ? d : 1);
    ax *= inv; ay *= inv; az *= inv; aw *= inv;
    __nv_bfloat16 hx = __float2bfloat16(ax), hy = __float2bfloat16(ay);
    __nv_bfloat16 hz = __float2bfloat16(az), hw = __float2bfloat16(aw);
    uint2 hi = make_uint2(bfpair(hx, hy), bfpair(hz, hw));
    uint2 lo = make_uint2(packbf(ax - __bfloat162float(hx), ay - __bfloat162float(hy)),
                          packbf(az - __bfloat162float(hz), aw - __bfloat162float(hw)));
    ((uint2*)g_nh4)[(size_t)w * 32 + lane] = hi;
    ((uint2*)g_nl4)[(size_t)w * 32 + lane] = lo;
}

// ================= WMMA bf16 GEMM + bias + LayerNorm + ReLU ====================
// CTA = 128 rows x 128 cols, 256 threads = 8 warps (warp tile 32x64).
// All 4 B weight tiles resident in smem for the whole CTA (no re-staging).
// A staged 2-at-a-time: [xh,xl] then [nh,nl]. Grouped passes share B fragments:
//   G1: B=Wsh x {xh,xl}   G2: B=Wsl x {xh}   G3: B=Wnh x {nh,nl}   G4: B=Wnl x {nh}
// All groups accumulate into one fp32 accumulator set.
#define LDA 136
#define ATILE (128 * LDA * 2)                // 34816 bytes
#define SM_BIAS  0
#define SM_GAMMA 512
#define SM_BETA  1024
#define SM_A     2048
#define A_T0 (SM_A + 0 * ATILE)              // xh, later nh (also fp32 out stage)
#define A_T1 (SM_A + 1 * ATILE)              // xl, later nl
#define SM_B (SM_A + 2 * ATILE)
#define B_TILE(t) (SM_B + (t) * ATILE)       // 0=Wsh 1=Wsl 2=Wnh 3=Wnl
#define SMEM_TOTAL (SM_B + 4 * ATILE)        // 210944 bytes
#define SM_F  SM_A                           // fp32 out buffer (reuses A tiles)

__global__ void __launch_bounds__(256, 1)
k_mm(const float* __restrict__ x,
     const float* __restrict__ bias,
     const float* __restrict__ gamma,
     const float* __restrict__ beta,
     float* __restrict__ out) {
    extern __shared__ char smem[];
    int tid = threadIdx.x;
    int wid = tid >> 5;

    if (tid < DD) {
        ((float*)(smem + SM_BIAS))[tid] = bias[tid];
        ((float*)(smem + SM_GAMMA))[tid] = gamma[tid];
        ((float*)(smem + SM_BETA))[tid] = beta[tid];
    }

    size_t g0 = (size_t)blockIdx.x * 128;
    int m = tid >> 1;             // row 0..127 (2 threads per row)
    int half = tid & 1;           // 64-element half

    // ---- stage all 4 B tiles (once per CTA) -----------------------------------
    {
        const uint4* wsrc = g_wall4 + m * 16 + half * 8;
#pragma unroll
        for (int t = 0; t < 4; t++) {
            uint4 r[8];
            const uint4* s = wsrc + t * 2048;
#pragma unroll
            for (int i = 0; i < 8; i++) r[i] = s[i];
            uint4* d = (uint4*)(smem + B_TILE(t) + m * (LDA * 2) + half * 128);
#pragma unroll
            for (int i = 0; i < 8; i++) d[i] = r[i];
        }
    }

    // ---- stage A = xh/xl (fp32 -> bf16 hi/lo split fused) ---------------------
    {
        const uint4* xs = (const uint4*)x + (g0 + m) * 32 + half * 16;
        uint4 hi[8], lo[8];
#pragma unroll
        for (int i = 0; i < 16; i++) {
            uint4 u = xs[i];
            float f0 = __uint_as_float(u.x), f1 = __uint_as_float(u.y);
            float f2 = __uint_as_float(u.z), f3 = __uint_as_float(u.w);
            __nv_bfloat16 h0 = __float2bfloat16(f0), h1 = __float2bfloat16(f1);
            __nv_bfloat16 h2 = __float2bfloat16(f2), h3 = __float2bfloat16(f3);
            ((uint32_t*)hi)[2 * i] = bfpair(h0, h1);
            ((uint32_t*)hi)[2 * i + 1] = bfpair(h2, h3);
            ((uint32_t*)lo)[2 * i] = packbf(f0 - __bfloat162float(h0), f1 - __bfloat162float(h1));
            ((uint32_t*)lo)[2 * i + 1] = packbf(f2 - __bfloat162float(h2), f3 - __bfloat162float(h3));
        }
        uint4* dh = (uint4*)(smem + A_T0 + m * (LDA * 2) + half * 128);
        uint4* dl = (uint4*)(smem + A_T1 + m * (LDA * 2) + half * 128);
#pragma unroll
        for (int i = 0; i < 8; i++) { dh[i] = hi[i]; dl[i] = lo[i]; }
    }
    __syncthreads();

    // ---- WMMA grouped passes --------------------------------------------------
    int wm = wid & 3, wn = wid >> 2;
    int row0 = wm * 32, col0 = wn * 64;

    wmma::fragment<wmma::accumulator, 16, 16, 16, float> fc[2][4];
#pragma unroll
    for (int i = 0; i < 2; i++)
#pragma unroll
        for (int j = 0; j < 4; j++) wmma::fill_fragment(fc[i][j], 0.0f);

// two A tiles vs one B tile: B fragments loaded once, 16 mmas per kk
#define GROUP2(AOFF0, AOFF1, BOFF) do {                                           \
    const __nv_bfloat16* _a0 = (const __nv_bfloat16*)(smem + (AOFF0));            \
    const __nv_bfloat16* _a1 = (const __nv_bfloat16*)(smem + (AOFF1));            \
    const __nv_bfloat16* _bb = (const __nv_bfloat16*)(smem + (BOFF));             \
    _Pragma("unroll")                                                             \
    for (int kk = 0; kk < 8; kk++) {                                              \
        wmma::fragment<wmma::matrix_b, 16, 16, 16, __nv_bfloat16, wmma::col_major> fb[4]; \
        wmma::fragment<wmma::matrix_a, 16, 16, 16, __nv_bfloat16, wmma::row_major> fa0[2], fa1[2]; \
        _Pragma("unroll")                                                         \
        for (int j = 0; j < 4; j++)                                               \
            wmma::load_matrix_sync(fb[j], _bb + (col0 + 16 * j) * LDA + kk * 16, LDA); \
        wmma::load_matrix_sync(fa0[0], _a0 + (row0 + 0) * LDA + kk * 16, LDA);    \
        wmma::load_matrix_sync(fa0[1], _a0 + (row0 + 16) * LDA + kk * 16, LDA);   \
        wmma::load_matrix_sync(fa1[0], _a1 + (row0 + 0) * LDA + kk * 16, LDA);    \
        wmma::load_matrix_sync(fa1[1], _a1 + (row0 + 16) * LDA + kk * 16, LDA);   \
        _Pragma("unroll")                                                         \
        for (int j = 0; j < 4; j++) {                                             \
            wmma::mma_sync(fc[0][j], fa0[0], fb[j], fc[0][j]);                    \
            wmma::mma_sync(fc[1][j], fa0[1], fb[j], fc[1][j]);                    \
            wmma::mma_sync(fc[0][j], fa1[0], fb[j], fc[0][j]);                    \
            wmma::mma_sync(fc[1][j], fa1[1], fb[j], fc[1][j]);                    \
        }                                                                         \
    }                                                                             \
} while (0)

#define GROUP1(AOFF0, BOFF) do {                                                  \
    const __nv_bfloat16* _a0 = (const __nv_bfloat16*)(smem + (AOFF0));            \
    const __nv_bfloat16* _bb = (const __nv_bfloat16*)(smem + (BOFF));             \
    _Pragma("unroll")                                                             \
    for (int kk = 0; kk < 8; kk++) {                                              \
        wmma::fragment<wmma::matrix_b, 16, 16, 16, __nv_bfloat16, wmma::col_major> fb[4]; \
        wmma::fragment<wmma::matrix_a, 16, 16, 16, __nv_bfloat16, wmma::row_major> fa0[2]; \
        _Pragma("unroll")                                                         \
        for (int j = 0; j < 4; j++)                                               \
            wmma::load_matrix_sync(fb[j], _bb + (col0 + 16 * j) * LDA + kk * 16, LDA); \
        wmma::load_matrix_sync(fa0[0], _a0 + (row0 + 0) * LDA + kk * 16, LDA);    \
        wmma::load_matrix_sync(fa0[1], _a0 + (row0 + 16) * LDA + kk * 16, LDA);   \
        _Pragma("unroll")                                                         \
        for (int j = 0; j < 4; j++) {                                             \
            wmma::mma_sync(fc[0][j], fa0[0], fb[j], fc[0][j]);                    \
            wmma::mma_sync(fc[1][j], fa0[1], fb[j], fc[1][j]);                    \
        }                                                                         \
    }                                                                             \
} while (0)

    GROUP2(A_T0, A_T1, B_TILE(0));   // xh,xl vs Wsh
    GROUP1(A_T0, B_TILE(1));         // xh vs Wsl
    __syncthreads();

    // ---- restage A = nh/nl ----------------------------------------------------
    {
        const uint4* nh = g_nh4 + (g0 + m) * 16 + half * 8;
        const uint4* nl = g_nl4 + (g0 + m) * 16 + half * 8;
        uint4 rh[8], rl[8];
#pragma unroll
        for (int i = 0; i < 8; i++) { rh[i] = nh[i]; rl[i] = nl[i]; }
        uint4* dnh = (uint4*)(smem + A_T0 + m * (LDA * 2) + half * 128);
        uint4* dnl = (uint4*)(smem + A_T1 + m * (LDA * 2) + half * 128);
#pragma unroll
        for (int i = 0; i < 8; i++) { dnh[i] = rh[i]; dnl[i] = rl[i]; }
    }
    __syncthreads();

    GROUP2(A_T0, A_T1, B_TILE(2));   // nh,nl vs Wnh
    GROUP1(A_T0, B_TILE(3));         // nh vs Wnl
    __syncthreads();

    // ---- store accum to smem fp32 (reuses A tile space) -----------------------
    float* fsm = (float*)(smem + SM_F);
#pragma unroll
    for (int i = 0; i < 2; i++)
#pragma unroll
        for (int j = 0; j < 4; j++)
            wmma::store_matrix_sync(fsm + (row0 + 16 * i) * 128 + col0 + 16 * j,
                                    fc[i][j], 128, wmma::mem_row_major);
    __syncthreads();

    // ---- bias + LayerNorm + ReLU + store --------------------------------------
    {
        const float* src = fsm + m * 128 + half * 64;
        const float* bs = (const float*)(smem + SM_BIAS) + half * 64;
        float v[64];
        float s = 0.f, ss = 0.f;
#pragma unroll
        for (int c = 0; c < 64; c++) {
            float t = src[c] + bs[c];
            v[c] = t;
            s += t;
            ss += t * t;
        }
        // partner (tid^1) holds the other half of this row — same warp
        s  += __shfl_xor_sync(0xFFFFFFFFu, s, 1);
        ss += __shfl_xor_sync(0xFFFFFFFFu, ss, 1);
        float mean = s * (1.0f / DD);
        float var = ss * (1.0f / DD) - mean * mean;
        float rstd = rsqrtf(var + LN_EPS);
        const float* gs = (const float*)(smem + SM_GAMMA) + half * 64;
        const float* bt = (const float*)(smem + SM_BETA) + half * 64;
        float4* orow = (float4*)(out + (g0 + m) * DD + half * 64);
#pragma unroll
        for (int c4 = 0; c4 < 16; c4++) {
            float v0 = (v[4 * c4 + 0] - mean) * rstd * gs[4 * c4 + 0] + bt[4 * c4 + 0];
            float v1 = (v[4 * c4 + 1] - mean) * rstd * gs[4 * c4 + 1] + bt[4 * c4 + 1];
            float v2 = (v[4 * c4 + 2] - mean) * rstd * gs[4 * c4 + 2] + bt[4 * c4 + 2];
            float v3 = (v[4 * c4 + 3] - mean) * rstd * gs[4 * c4 + 3] + bt[4 * c4 + 3];
            float4 ov;
            ov.x = v0 > 0.f ? v0 : 0.f;
            ov.y = v1 > 0.f ? v1 : 0.f;
            ov.z = v2 > 0.f ? v2 : 0.f;
            ov.w = v3 > 0.f ? v3 : 0.f;
            orow[c4] = ov;
        }
    }
}

// ================= launch ======================================================
extern "C" void kernel_launch(void* const* d_in, const int* in_sizes, int n_in,
                              void* d_out, int out_size) {
    const float* x = nullptr;
    const int* edge = nullptr;
    const float* Wself = nullptr;
    const float* Wneigh = nullptr;
    const float* bias = nullptr;
    const float* gamma = nullptr;
    const float* beta = nullptr;
    int nW = 0, nV = 0;
    for (int i = 0; i < n_in; i++) {
        int s = in_sizes[i];
        if (s == NODES * DD) {
            if (!x) x = (const float*)d_in[i];
        } else if (s == 2 * EE || s == 4 * EE) {
            edge = (const int*)d_in[i];
        } else if (s == DD * DD) {
            if (nW == 0) Wself = (const float*)d_in[i];
            else if (nW == 1) Wneigh = (const float*)d_in[i];
            nW++;
        } else if (s == DD) {
            if (nV == 0) bias = (const float*)d_in[i];
            else if (nV == 1) gamma = (const float*)d_in[i];
            else if (nV == 2) beta = (const float*)d_in[i];
            nV++;
        }
    }

    cudaFuncSetAttribute(k_mm, cudaFuncAttributeMaxDynamicSharedMemorySize, SMEM_TOTAL);

    // exactly 6 launches: k_mm is launch #6 (ncu -s 5 -c 1 captures it)
    k_init<<<EE / 256, 256>>>(edge, Wself, Wneigh);
    k_count<<<EE / 256, 256>>>(edge);
    k_scan<<<1, 1024>>>();
    k_fill<<<EE / 256, 256>>>(edge);
    k_agg<<<(NODES * 32) / 256, 256>>>(x);
    k_mm<<<NODES / 128, 256, SMEM_TOTAL>>>(x, bias, gamma, beta, (float*)d_out);
}

// round 8
// speedup vs baseline: 1.3836x; 1.2685x over previous
#include <cuda_runtime.h>
#include <cuda_fp16.h>
#include <mma.h>
#include <cstdint>

using namespace nvcuda;

// Problem constants (fixed by the dataset)
#define BB 16
#define NN 16384
#define DD 128
#define EE 65536
#define NODES (BB * NN)          // 262144
#define LN_EPS 1e-5f

// ================= scratch (__device__ globals) ================================
__device__ int g_is32;
__device__ __align__(16) int g_deg[NN];
__device__ __align__(16) int g_rowptr[NN + 1];
__device__ __align__(16) int g_cursor[NN];
__device__ int g_csr[EE];
__device__ uint4 g_n4[(size_t)NODES * 16];    // neigh fp16 rows (256B each) = 64MB
__device__ uint4 g_w4[4096];                  // [128 n][256 k] fp16: Ws|Wn concat

__device__ __forceinline__ int clampN(int v) {
    return v < 0 ? 0 : (v >= NN ? NN - 1 : v);
}
__device__ __forceinline__ int edge_src(const int* e32, int e) {
    return clampN(g_is32 ? e32[e] : e32[2 * e]);
}
__device__ __forceinline__ int edge_dst(const int* e32, int e) {
    return clampN(g_is32 ? e32[EE + e] : e32[2 * EE + 2 * e]);
}
__device__ __forceinline__ uint32_t packh(float a, float b) {
    __half2 t(__float2half_rn(a), __float2half_rn(b));
    return *reinterpret_cast<uint32_t*>(&t);
}

// ================= fused init: zero degrees + dtype detect + weight convert ====
__global__ void k_init(const int* __restrict__ e32,
                       const float* __restrict__ Ws, const float* __restrict__ Wn) {
    int i = blockIdx.x * blockDim.x + threadIdx.x;
    if (i == 0) g_is32 = 0;
    if (i < NN) g_deg[i] = 0;
    if (i < EE && e32[2 * i + 1] != 0) g_is32 = 1;
    if (i < DD * DD) {
        __half* w = (__half*)g_w4;
        int n = i >> 7, k = i & 127;
        w[n * 256 + k] = __float2half_rn(Ws[i]);
        w[n * 256 + 128 + k] = __float2half_rn(Wn[i]);
    }
}

__global__ void k_count(const int* __restrict__ e32) {
    int e = blockIdx.x * blockDim.x + threadIdx.x;
    if (e < EE) atomicAdd(&g_deg[edge_dst(e32, e)], 1);
}

// vectorized single-block scan: 1024 threads x 16 elems, warp shuffles
__global__ void k_scan() {
    __shared__ int wsum[32], wpre[32];
    int t = threadIdx.x, lane = t & 31, w = t >> 5;
    const int4* dg = (const int4*)g_deg;
    int loc[16];
#pragma unroll
    for (int q = 0; q < 4; q++) {
        int4 v = dg[t * 4 + q];
        loc[4 * q + 0] = v.x; loc[4 * q + 1] = v.y;
        loc[4 * q + 2] = v.z; loc[4 * q + 3] = v.w;
    }
    int s = 0;
#pragma unroll
    for (int m = 0; m < 16; m++) s += loc[m];
    int inc = s;
#pragma unroll
    for (int o = 1; o < 32; o <<= 1) {
        int u = __shfl_up_sync(0xFFFFFFFFu, inc, o);
        if (lane >= o) inc += u;
    }
    if (lane == 31) wsum[w] = inc;
    __syncthreads();
    if (w == 0) {
        int a = wsum[lane], ai = a;
#pragma unroll
        for (int o = 1; o < 32; o <<= 1) {
            int u = __shfl_up_sync(0xFFFFFFFFu, ai, o);
            if (lane >= o) ai += u;
        }
        wpre[lane] = ai - a;
    }
    __syncthreads();
    int run = wpre[w] + (inc - s);
    int rp[16];
#pragma unroll
    for (int m = 0; m < 16; m++) { rp[m] = run; run += loc[m]; }
    int4* rpo = (int4*)g_rowptr;
    int4* cu = (int4*)g_cursor;
#pragma unroll
    for (int q = 0; q < 4; q++) {
        int4 o4 = make_int4(rp[4 * q], rp[4 * q + 1], rp[4 * q + 2], rp[4 * q + 3]);
        rpo[t * 4 + q] = o4;
        cu[t * 4 + q] = o4;
    }
    if (t == 1023) g_rowptr[NN] = run;
}

__global__ void k_fill(const int* __restrict__ e32) {
    int e = blockIdx.x * blockDim.x + threadIdx.x;
    if (e < EE) {
        int d = edge_dst(e32, e);
        int pos = atomicAdd(&g_cursor[d], 1);
        if (pos >= 0 && pos < EE) g_csr[pos] = edge_src(e32, e);
    }
}

// ================= neighbor mean aggregation (writes fp16) =====================
__global__ void k_agg(const float* __restrict__ x) {
    int t = blockIdx.x * blockDim.x + threadIdx.x;
    int w = t >> 5;           // (batch,node) id in [0, NODES)
    int lane = t & 31;
    int b = w >> 14;
    int n = w & (NN - 1);
    int s0 = g_rowptr[n];
    int s1 = g_rowptr[n + 1];
    const float4* xb = (const float4*)x + (size_t)b * NN * 32;
    float ax = 0.f, ay = 0.f, az = 0.f, aw = 0.f;
    for (int e = s0; e < s1; e++) {
        float4 v = xb[(size_t)g_csr[e] * 32 + lane];
        ax += v.x; ay += v.y; az += v.z; aw += v.w;
    }
    int d = s1 - s0;
    float inv = 1.0f / (float)(d > 0 ? d : 1);
    uint2 r = make_uint2(packh(ax * inv, ay * inv), packh(az * inv, aw * inv));
    ((uint2*)g_n4)[(size_t)w * 32 + lane] = r;
}

// ================= WMMA fp16 GEMM (K=256) + bias + LayerNorm + ReLU ============
// CTA = 128 rows x 128 cols, 512 threads = 16 warps (warp tile 32x32).
// A = [x_fp16 | neigh_fp16] (128 x 256), B = [Ws | Wn] rows (128 n x 256 k).
// Single pass: out = A @ B^T, fp32 accum.
#define LDAB 264                              // fp16 elems per row (256 + 8 pad)
#define ABYTES (128 * LDAB * 2)               // 67584
#define SM_BIAS  0
#define SM_GAMMA 512
#define SM_BETA  1024
#define SM_A     2048
#define SM_B     (SM_A + ABYTES)
#define SMEM_TOTAL (SM_B + ABYTES)            // 137216
#define SM_F     SM_A                         // fp32 out stage (stride 132) reuses A
#define LDF      132

__global__ void __launch_bounds__(512, 1)
k_mm(const float* __restrict__ x,
     const float* __restrict__ bias,
     const float* __restrict__ gamma,
     const float* __restrict__ beta,
     float* __restrict__ out) {
    extern __shared__ char smem[];
    int tid = threadIdx.x;
    int wid = tid >> 5;

    if (tid < DD) {
        ((float*)(smem + SM_BIAS))[tid] = bias[tid];
        ((float*)(smem + SM_GAMMA))[tid] = gamma[tid];
        ((float*)(smem + SM_BETA))[tid] = beta[tid];
    }

    size_t g0 = (size_t)blockIdx.x * 128;
    int row = tid >> 2;           // 0..127
    int q = tid & 3;              // quarter of a row

    // ---- stage B: 128 rows x 512B (once per CTA) ------------------------------
#pragma unroll
    for (int i = 0; i < 8; i++) {
        int idx = tid + 512 * i;            // 0..4095
        int r = idx >> 5, c = idx & 31;
        *(uint4*)(smem + SM_B + r * (LDAB * 2) + c * 16) = g_w4[idx];
    }

    // ---- stage A: x -> fp16 (cols 0..127), neigh fp16 copy (cols 128..255) ----
    {
        const float4* xs = (const float4*)x + (g0 + row) * 32 + q * 8;
        uint32_t h[16];
#pragma unroll
        for (int i = 0; i < 8; i++) {
            float4 u = xs[i];
            h[2 * i] = packh(u.x, u.y);
            h[2 * i + 1] = packh(u.z, u.w);
        }
        uint4* d = (uint4*)(smem + SM_A + row * (LDAB * 2) + q * 64);
#pragma unroll
        for (int i = 0; i < 4; i++)
            d[i] = make_uint4(h[4 * i], h[4 * i + 1], h[4 * i + 2], h[4 * i + 3]);
    }
#pragma unroll
    for (int i = 0; i < 4; i++) {
        int idx = tid + 512 * i;            // 0..2047
        int r = idx >> 4, c = idx & 15;
        *(uint4*)(smem + SM_A + r * (LDAB * 2) + 256 + c * 16) =
            g_n4[(g0 + r) * 16 + c];
    }
    __syncthreads();

    // ---- single-pass WMMA: 16 kk steps ----------------------------------------
    int wm = wid & 3, wn = wid >> 2;
    int row0 = wm * 32, col0 = wn * 32;

    wmma::fragment<wmma::accumulator, 16, 16, 16, float> fc[2][2];
#pragma unroll
    for (int i = 0; i < 2; i++)
#pragma unroll
        for (int j = 0; j < 2; j++) wmma::fill_fragment(fc[i][j], 0.0f);

    const __half* ab = (const __half*)(smem + SM_A);
    const __half* bb = (const __half*)(smem + SM_B);
#pragma unroll
    for (int kk = 0; kk < 16; kk++) {
        wmma::fragment<wmma::matrix_a, 16, 16, 16, __half, wmma::row_major> fa[2];
        wmma::fragment<wmma::matrix_b, 16, 16, 16, __half, wmma::col_major> fb[2];
        wmma::load_matrix_sync(fa[0], ab + (row0 + 0) * LDAB + kk * 16, LDAB);
        wmma::load_matrix_sync(fa[1], ab + (row0 + 16) * LDAB + kk * 16, LDAB);
        wmma::load_matrix_sync(fb[0], bb + (col0 + 0) * LDAB + kk * 16, LDAB);
        wmma::load_matrix_sync(fb[1], bb + (col0 + 16) * LDAB + kk * 16, LDAB);
#pragma unroll
        for (int i = 0; i < 2; i++)
#pragma unroll
            for (int j = 0; j < 2; j++)
                wmma::mma_sync(fc[i][j], fa[i], fb[j], fc[i][j]);
    }
    __syncthreads();   // done reading A region before overwriting with fp32 stage

    // ---- store accum to smem fp32 ---------------------------------------------
    float* fsm = (float*)(smem + SM_F);
#pragma unroll
    for (int i = 0; i < 2; i++)
#pragma unroll
        for (int j = 0; j < 2; j++)
            wmma::store_matrix_sync(fsm + (row0 + 16 * i) * LDF + col0 + 16 * j,
                                    fc[i][j], LDF, wmma::mem_row_major);
    __syncthreads();

    // ---- bias + LayerNorm + ReLU + store --------------------------------------
    {
        const float* src = fsm + row * LDF + q * 32;
        const float* bs = (const float*)(smem + SM_BIAS) + q * 32;
        float v[32];
        float s = 0.f, ss = 0.f;
#pragma unroll
        for (int c = 0; c < 32; c++) {
            float t = src[c] + bs[c];
            v[c] = t;
            s += t;
            ss += t * t;
        }
        // 4 consecutive lanes share a row: combine quarters
        s  += __shfl_xor_sync(0xFFFFFFFFu, s, 1);
        ss += __shfl_xor_sync(0xFFFFFFFFu, ss, 1);
        s  += __shfl_xor_sync(0xFFFFFFFFu, s, 2);
        ss += __shfl_xor_sync(0xFFFFFFFFu, ss, 2);
        float mean = s * (1.0f / DD);
        float var = ss * (1.0f / DD) - mean * mean;
        float rstd = rsqrtf(var + LN_EPS);
        const float* gs = (const float*)(smem + SM_GAMMA) + q * 32;
        const float* bt = (const float*)(smem + SM_BETA) + q * 32;
        float4* orow = (float4*)(out + (g0 + row) * DD + q * 32);
#pragma unroll
        for (int c4 = 0; c4 < 8; c4++) {
            float v0 = (v[4 * c4 + 0] - mean) * rstd * gs[4 * c4 + 0] + bt[4 * c4 + 0];
            float v1 = (v[4 * c4 + 1] - mean) * rstd * gs[4 * c4 + 1] + bt[4 * c4 + 1];
            float v2 = (v[4 * c4 + 2] - mean) * rstd * gs[4 * c4 + 2] + bt[4 * c4 + 2];
            float v3 = (v[4 * c4 + 3] - mean) * rstd * gs[4 * c4 + 3] + bt[4 * c4 + 3];
            float4 ov;
            ov.x = v0 > 0.f ? v0 : 0.f;
            ov.y = v1 > 0.f ? v1 : 0.f;
            ov.z = v2 > 0.f ? v2 : 0.f;
            ov.w = v3 > 0.f ? v3 : 0.f;
            orow[c4] = ov;
        }
    }
}

// ================= launch ======================================================
extern "C" void kernel_launch(void* const* d_in, const int* in_sizes, int n_in,
                              void* d_out, int out_size) {
    const float* x = nullptr;
    const int* edge = nullptr;
    const float* Wself = nullptr;
    const float* Wneigh = nullptr;
    const float* bias = nullptr;
    const float* gamma = nullptr;
    const float* beta = nullptr;
    int nW = 0, nV = 0;
    for (int i = 0; i < n_in; i++) {
        int s = in_sizes[i];
        if (s == NODES * DD) {
            if (!x) x = (const float*)d_in[i];
        } else if (s == 2 * EE || s == 4 * EE) {
            edge = (const int*)d_in[i];
        } else if (s == DD * DD) {
            if (nW == 0) Wself = (const float*)d_in[i];
            else if (nW == 1) Wneigh = (const float*)d_in[i];
            nW++;
        } else if (s == DD) {
            if (nV == 0) bias = (const float*)d_in[i];
            else if (nV == 1) gamma = (const float*)d_in[i];
            else if (nV == 2) beta = (const float*)d_in[i];
            nV++;
        }
    }

    cudaFuncSetAttribute(k_mm, cudaFuncAttributeMaxDynamicSharedMemorySize, SMEM_TOTAL);

    k_init<<<EE / 256, 256>>>(edge, Wself, Wneigh);
    k_count<<<EE / 256, 256>>>(edge);
    k_scan<<<1, 1024>>>();
    k_fill<<<EE / 256, 256>>>(edge);
    k_agg<<<(NODES * 32) / 256, 256>>>(x);
    k_mm<<<NODES / 128, 512, SMEM_TOTAL>>>(x, bias, gamma, beta, (float*)d_out);
}

// round 9
// speedup vs baseline: 2.0658x; 1.4931x over previous
#include <cuda_runtime.h>
#include <cuda_fp16.h>
#include <mma.h>
#include <cstdint>

using namespace nvcuda;

// Problem constants (fixed by the dataset)
#define BB 16
#define NN 16384
#define DD 128
#define EE 65536
#define NODES (BB * NN)          // 262144
#define LN_EPS 1e-5f

// ================= scratch (__device__ globals) ================================
__device__ int g_is32;
__device__ __align__(16) int g_deg[NN];
__device__ __align__(16) int g_rowptr[NN + 1];
__device__ __align__(16) int g_cursor[NN];
__device__ int g_csr[EE];
__device__ uint4 g_xh[(size_t)NODES * 16];    // x as fp16 rows (256B each) = 64MB
__device__ uint4 g_n4[(size_t)NODES * 16];    // neigh fp16 rows (256B each) = 64MB
__device__ uint4 g_w4[4096];                  // [128 n][256 k] fp16: Ws|Wn concat

__device__ __forceinline__ int clampN(int v) {
    return v < 0 ? 0 : (v >= NN ? NN - 1 : v);
}
__device__ __forceinline__ int edge_src(const int* e32, int e) {
    return clampN(g_is32 ? e32[e] : e32[2 * e]);
}
__device__ __forceinline__ int edge_dst(const int* e32, int e) {
    return clampN(g_is32 ? e32[EE + e] : e32[2 * EE + 2 * e]);
}
__device__ __forceinline__ uint32_t packh(float a, float b) {
    __half2 t(__float2half_rn(a), __float2half_rn(b));
    return *reinterpret_cast<uint32_t*>(&t);
}

// ================= fused init: zero degrees + dtype detect + weight convert ====
__global__ void k_init(const int* __restrict__ e32,
                       const float* __restrict__ Ws, const float* __restrict__ Wn) {
    int i = blockIdx.x * blockDim.x + threadIdx.x;
    if (i == 0) g_is32 = 0;
    if (i < NN) g_deg[i] = 0;
    if (i < EE && e32[2 * i + 1] != 0) g_is32 = 1;
    if (i < DD * DD) {
        __half* w = (__half*)g_w4;
        int n = i >> 7, k = i & 127;
        w[n * 256 + k] = __float2half_rn(Ws[i]);
        w[n * 256 + 128 + k] = __float2half_rn(Wn[i]);
    }
}

__global__ void k_count(const int* __restrict__ e32) {
    int e = blockIdx.x * blockDim.x + threadIdx.x;
    if (e < EE) atomicAdd(&g_deg[edge_dst(e32, e)], 1);
}

// vectorized single-block scan: 1024 threads x 16 elems, warp shuffles
__global__ void k_scan() {
    __shared__ int wsum[32], wpre[32];
    int t = threadIdx.x, lane = t & 31, w = t >> 5;
    const int4* dg = (const int4*)g_deg;
    int loc[16];
#pragma unroll
    for (int q = 0; q < 4; q++) {
        int4 v = dg[t * 4 + q];
        loc[4 * q + 0] = v.x; loc[4 * q + 1] = v.y;
        loc[4 * q + 2] = v.z; loc[4 * q + 3] = v.w;
    }
    int s = 0;
#pragma unroll
    for (int m = 0; m < 16; m++) s += loc[m];
    int inc = s;
#pragma unroll
    for (int o = 1; o < 32; o <<= 1) {
        int u = __shfl_up_sync(0xFFFFFFFFu, inc, o);
        if (lane >= o) inc += u;
    }
    if (lane == 31) wsum[w] = inc;
    __syncthreads();
    if (w == 0) {
        int a = wsum[lane], ai = a;
#pragma unroll
        for (int o = 1; o < 32; o <<= 1) {
            int u = __shfl_up_sync(0xFFFFFFFFu, ai, o);
            if (lane >= o) ai += u;
        }
        wpre[lane] = ai - a;
    }
    __syncthreads();
    int run = wpre[w] + (inc - s);
    int rp[16];
#pragma unroll
    for (int m = 0; m < 16; m++) { rp[m] = run; run += loc[m]; }
    int4* rpo = (int4*)g_rowptr;
    int4* cu = (int4*)g_cursor;
#pragma unroll
    for (int q = 0; q < 4; q++) {
        int4 o4 = make_int4(rp[4 * q], rp[4 * q + 1], rp[4 * q + 2], rp[4 * q + 3]);
        rpo[t * 4 + q] = o4;
        cu[t * 4 + q] = o4;
    }
    if (t == 1023) g_rowptr[NN] = run;
}

__global__ void k_fill(const int* __restrict__ e32) {
    int e = blockIdx.x * blockDim.x + threadIdx.x;
    if (e < EE) {
        int d = edge_dst(e32, e);
        int pos = atomicAdd(&g_cursor[d], 1);
        if (pos >= 0 && pos < EE) g_csr[pos] = edge_src(e32, e);
    }
}

// ================= x -> fp16 conversion (streaming) ============================
// thread handles 8 consecutive floats -> one uint4 of 8 halves
__global__ void k_xh(const float* __restrict__ x) {
    size_t i = (size_t)blockIdx.x * blockDim.x + threadIdx.x;   // < NODES*16
    const float4* s = (const float4*)x + 2 * i;
    float4 a = s[0], b = s[1];
    g_xh[i] = make_uint4(packh(a.x, a.y), packh(a.z, a.w),
                         packh(b.x, b.y), packh(b.z, b.w));
}

// ================= neighbor mean aggregation (fp16 gather, L2-resident) ========
// one warp per (batch, node); lane handles 4 halves (uint2 = 8B)
__global__ void k_agg() {
    int t = blockIdx.x * blockDim.x + threadIdx.x;
    int w = t >> 5;           // (batch,node) id in [0, NODES)
    int lane = t & 31;
    int b = w >> 14;
    int n = w & (NN - 1);
    int s0 = g_rowptr[n];
    int s1 = g_rowptr[n + 1];
    const uint2* xb = (const uint2*)g_xh + (size_t)b * NN * 32;
    float a0 = 0.f, a1 = 0.f, a2 = 0.f, a3 = 0.f;
    for (int e = s0; e < s1; e++) {
        uint2 v = xb[(size_t)g_csr[e] * 32 + lane];
        float2 p0 = __half22float2(*reinterpret_cast<__half2*>(&v.x));
        float2 p1 = __half22float2(*reinterpret_cast<__half2*>(&v.y));
        a0 += p0.x; a1 += p0.y; a2 += p1.x; a3 += p1.y;
    }
    int d = s1 - s0;
    float inv = 1.0f / (float)(d > 0 ? d : 1);
    uint2 r = make_uint2(packh(a0 * inv, a1 * inv), packh(a2 * inv, a3 * inv));
    ((uint2*)g_n4)[(size_t)w * 32 + lane] = r;
}

// ================= WMMA fp16 GEMM (K=256) + bias + LayerNorm + ReLU ============
// CTA = 128 rows x 128 cols, 512 threads = 16 warps (warp tile 32x32).
// A = [x_fp16 | neigh_fp16] (128 x 256), B = [Ws | Wn] rows (128 n x 256 k).
// Single pass: out = A @ B^T, fp32 accum.
#define LDAB 264                              // fp16 elems per row (256 + 8 pad)
#define ABYTES (128 * LDAB * 2)               // 67584
#define SM_BIAS  0
#define SM_GAMMA 512
#define SM_BETA  1024
#define SM_A     2048
#define SM_B     (SM_A + ABYTES)
#define SMEM_TOTAL (SM_B + ABYTES)            // 137216
#define SM_F     SM_A                         // fp32 out stage (stride 132) reuses A
#define LDF      132

__global__ void __launch_bounds__(512, 1)
k_mm(const float* __restrict__ bias,
     const float* __restrict__ gamma,
     const float* __restrict__ beta,
     float* __restrict__ out) {
    extern __shared__ char smem[];
    int tid = threadIdx.x;
    int wid = tid >> 5;

    if (tid < DD) {
        ((float*)(smem + SM_BIAS))[tid] = bias[tid];
        ((float*)(smem + SM_GAMMA))[tid] = gamma[tid];
        ((float*)(smem + SM_BETA))[tid] = beta[tid];
    }

    size_t g0 = (size_t)blockIdx.x * 128;
    int row = tid >> 2;           // 0..127
    int q = tid & 3;              // quarter of a row

    // ---- stage B: 128 rows x 512B (once per CTA) ------------------------------
#pragma unroll
    for (int i = 0; i < 8; i++) {
        int idx = tid + 512 * i;            // 0..4095
        int r = idx >> 5, c = idx & 31;
        *(uint4*)(smem + SM_B + r * (LDAB * 2) + c * 16) = g_w4[idx];
    }

    // ---- stage A: x fp16 (cols 0..127) + neigh fp16 (cols 128..255) -----------
#pragma unroll
    for (int i = 0; i < 4; i++) {
        int idx = tid + 512 * i;            // 0..2047
        int r = idx >> 4, c = idx & 15;
        *(uint4*)(smem + SM_A + r * (LDAB * 2) + c * 16) = g_xh[(g0 + r) * 16 + c];
        *(uint4*)(smem + SM_A + r * (LDAB * 2) + 256 + c * 16) = g_n4[(g0 + r) * 16 + c];
    }
    __syncthreads();

    // ---- single-pass WMMA: 16 kk steps ----------------------------------------
    int wm = wid & 3, wn = wid >> 2;
    int row0 = wm * 32, col0 = wn * 32;

    wmma::fragment<wmma::accumulator, 16, 16, 16, float> fc[2][2];
#pragma unroll
    for (int i = 0; i < 2; i++)
#pragma unroll
        for (int j = 0; j < 2; j++) wmma::fill_fragment(fc[i][j], 0.0f);

    const __half* ab = (const __half*)(smem + SM_A);
    const __half* bb = (const __half*)(smem + SM_B);
#pragma unroll
    for (int kk = 0; kk < 16; kk++) {
        wmma::fragment<wmma::matrix_a, 16, 16, 16, __half, wmma::row_major> fa[2];
        wmma::fragment<wmma::matrix_b, 16, 16, 16, __half, wmma::col_major> fb[2];
        wmma::load_matrix_sync(fa[0], ab + (row0 + 0) * LDAB + kk * 16, LDAB);
        wmma::load_matrix_sync(fa[1], ab + (row0 + 16) * LDAB + kk * 16, LDAB);
        wmma::load_matrix_sync(fb[0], bb + (col0 + 0) * LDAB + kk * 16, LDAB);
        wmma::load_matrix_sync(fb[1], bb + (col0 + 16) * LDAB + kk * 16, LDAB);
#pragma unroll
        for (int i = 0; i < 2; i++)
#pragma unroll
            for (int j = 0; j < 2; j++)
                wmma::mma_sync(fc[i][j], fa[i], fb[j], fc[i][j]);
    }
    __syncthreads();   // done reading A region before overwriting with fp32 stage

    // ---- store accum to smem fp32 ---------------------------------------------
    float* fsm = (float*)(smem + SM_F);
#pragma unroll
    for (int i = 0; i < 2; i++)
#pragma unroll
        for (int j = 0; j < 2; j++)
            wmma::store_matrix_sync(fsm + (row0 + 16 * i) * LDF + col0 + 16 * j,
                                    fc[i][j], LDF, wmma::mem_row_major);
    __syncthreads();

    // ---- bias + LayerNorm + ReLU + store --------------------------------------
    {
        const float* src = fsm + row * LDF + q * 32;
        const float* bs = (const float*)(smem + SM_BIAS) + q * 32;
        float v[32];
        float s = 0.f, ss = 0.f;
#pragma unroll
        for (int c = 0; c < 32; c++) {
            float t = src[c] + bs[c];
            v[c] = t;
            s += t;
            ss += t * t;
        }
        // 4 consecutive lanes share a row: combine quarters
        s  += __shfl_xor_sync(0xFFFFFFFFu, s, 1);
        ss += __shfl_xor_sync(0xFFFFFFFFu, ss, 1);
        s  += __shfl_xor_sync(0xFFFFFFFFu, s, 2);
        ss += __shfl_xor_sync(0xFFFFFFFFu, ss, 2);
        float mean = s * (1.0f / DD);
        float var = ss * (1.0f / DD) - mean * mean;
        float rstd = rsqrtf(var + LN_EPS);
        const float* gs = (const float*)(smem + SM_GAMMA) + q * 32;
        const float* bt = (const float*)(smem + SM_BETA) + q * 32;
        float4* orow = (float4*)(out + (g0 + row) * DD + q * 32);
#pragma unroll
        for (int c4 = 0; c4 < 8; c4++) {
            float v0 = (v[4 * c4 + 0] - mean) * rstd * gs[4 * c4 + 0] + bt[4 * c4 + 0];
            float v1 = (v[4 * c4 + 1] - mean) * rstd * gs[4 * c4 + 1] + bt[4 * c4 + 1];
            float v2 = (v[4 * c4 + 2] - mean) * rstd * gs[4 * c4 + 2] + bt[4 * c4 + 2];
            float v3 = (v[4 * c4 + 3] - mean) * rstd * gs[4 * c4 + 3] + bt[4 * c4 + 3];
            float4 ov;
            ov.x = v0 > 0.f ? v0 : 0.f;
            ov.y = v1 > 0.f ? v1 : 0.f;
            ov.z = v2 > 0.f ? v2 : 0.f;
            ov.w = v3 > 0.f ? v3 : 0.f;
            orow[c4] = ov;
        }
    }
}

// ================= launch ======================================================
extern "C" void kernel_launch(void* const* d_in, const int* in_sizes, int n_in,
                              void* d_out, int out_size) {
    const float* x = nullptr;
    const int* edge = nullptr;
    const float* Wself = nullptr;
    const float* Wneigh = nullptr;
    const float* bias = nullptr;
    const float* gamma = nullptr;
    const float* beta = nullptr;
    int nW = 0, nV = 0;
    for (int i = 0; i < n_in; i++) {
        int s = in_sizes[i];
        if (s == NODES * DD) {
            if (!x) x = (const float*)d_in[i];
        } else if (s == 2 * EE || s == 4 * EE) {
            edge = (const int*)d_in[i];
        } else if (s == DD * DD) {
            if (nW == 0) Wself = (const float*)d_in[i];
            else if (nW == 1) Wneigh = (const float*)d_in[i];
            nW++;
        } else if (s == DD) {
            if (nV == 0) bias = (const float*)d_in[i];
            else if (nV == 1) gamma = (const float*)d_in[i];
            else if (nV == 2) beta = (const float*)d_in[i];
            nV++;
        }
    }

    cudaFuncSetAttribute(k_mm, cudaFuncAttributeMaxDynamicSharedMemorySize, SMEM_TOTAL);

    k_init<<<EE / 256, 256>>>(edge, Wself, Wneigh);
    k_count<<<EE / 256, 256>>>(edge);
    k_scan<<<1, 1024>>>();
    k_fill<<<EE / 256, 256>>>(edge);
    k_xh<<<NODES * 16 / 256, 256>>>(x);
    k_agg<<<(NODES * 32) / 256, 256>>>();
    k_mm<<<NODES / 128, 512, SMEM_TOTAL>>>(bias, gamma, beta, (float*)d_out);
}

// round 10
// speedup vs baseline: 2.1855x; 1.0579x over previous
#include <cuda_runtime.h>
#include <cuda_fp16.h>
#include <mma.h>
#include <cstdint>

using namespace nvcuda;

// Problem constants (fixed by the dataset)
#define BB 16
#define NN 16384
#define DD 128
#define EE 65536
#define NODES (BB * NN)          // 262144
#define LN_EPS 1e-5f

// ================= scratch (__device__ globals) ================================
__device__ int g_is32;
__device__ __align__(16) int g_deg[NN];
__device__ __align__(16) int g_rowptr[NN + 1];
__device__ __align__(16) int g_cursor[NN];
__device__ int g_csr[EE];
__device__ uint4 g_xh[(size_t)NODES * 16];    // x as fp16 rows (256B each) = 64MB
__device__ uint4 g_w4[4096];                  // [128 n][256 k] fp16: Ws|Wn concat

__device__ __forceinline__ int clampN(int v) {
    return v < 0 ? 0 : (v >= NN ? NN - 1 : v);
}
__device__ __forceinline__ int edge_src(const int* e32, int e) {
    return clampN(g_is32 ? e32[e] : e32[2 * e]);
}
__device__ __forceinline__ int edge_dst(const int* e32, int e) {
    return clampN(g_is32 ? e32[EE + e] : e32[2 * EE + 2 * e]);
}
__device__ __forceinline__ uint32_t packh(float a, float b) {
    __half2 t(__float2half_rn(a), __float2half_rn(b));
    return *reinterpret_cast<uint32_t*>(&t);
}

// ================= fused init: zero degrees + dtype detect + weight convert ====
__global__ void k_init(const int* __restrict__ e32,
                       const float* __restrict__ Ws, const float* __restrict__ Wn) {
    int i = blockIdx.x * blockDim.x + threadIdx.x;
    if (i == 0) g_is32 = 0;
    if (i < NN) g_deg[i] = 0;
    if (i < EE && e32[2 * i + 1] != 0) g_is32 = 1;
    if (i < DD * DD) {
        __half* w = (__half*)g_w4;
        int n = i >> 7, k = i & 127;
        w[n * 256 + k] = __float2half_rn(Ws[i]);
        w[n * 256 + 128 + k] = __float2half_rn(Wn[i]);
    }
}

// ================= fused: degree count + x -> fp16 conversion ==================
// grid covers NODES*16 threads; first EE also do the degree atomics
__global__ void k_count_xh(const int* __restrict__ e32, const float* __restrict__ x) {
    size_t i = (size_t)blockIdx.x * blockDim.x + threadIdx.x;
    if (i < EE) atomicAdd(&g_deg[edge_dst(e32, (int)i)], 1);
    // x conversion: 8 consecutive floats -> one uint4 of 8 halves
    const float4* s = (const float4*)x + 2 * i;
    float4 a = s[0], b = s[1];
    g_xh[i] = make_uint4(packh(a.x, a.y), packh(a.z, a.w),
                         packh(b.x, b.y), packh(b.z, b.w));
}

// vectorized single-block scan: 1024 threads x 16 elems, warp shuffles
__global__ void k_scan() {
    __shared__ int wsum[32], wpre[32];
    int t = threadIdx.x, lane = t & 31, w = t >> 5;
    const int4* dg = (const int4*)g_deg;
    int loc[16];
#pragma unroll
    for (int q = 0; q < 4; q++) {
        int4 v = dg[t * 4 + q];
        loc[4 * q + 0] = v.x; loc[4 * q + 1] = v.y;
        loc[4 * q + 2] = v.z; loc[4 * q + 3] = v.w;
    }
    int s = 0;
#pragma unroll
    for (int m = 0; m < 16; m++) s += loc[m];
    int inc = s;
#pragma unroll
    for (int o = 1; o < 32; o <<= 1) {
        int u = __shfl_up_sync(0xFFFFFFFFu, inc, o);
        if (lane >= o) inc += u;
    }
    if (lane == 31) wsum[w] = inc;
    __syncthreads();
    if (w == 0) {
        int a = wsum[lane], ai = a;
#pragma unroll
        for (int o = 1; o < 32; o <<= 1) {
            int u = __shfl_up_sync(0xFFFFFFFFu, ai, o);
            if (lane >= o) ai += u;
        }
        wpre[lane] = ai - a;
    }
    __syncthreads();
    int run = wpre[w] + (inc - s);
    int rp[16];
#pragma unroll
    for (int m = 0; m < 16; m++) { rp[m] = run; run += loc[m]; }
    int4* rpo = (int4*)g_rowptr;
    int4* cu = (int4*)g_cursor;
#pragma unroll
    for (int q = 0; q < 4; q++) {
        int4 o4 = make_int4(rp[4 * q], rp[4 * q + 1], rp[4 * q + 2], rp[4 * q + 3]);
        rpo[t * 4 + q] = o4;
        cu[t * 4 + q] = o4;
    }
    if (t == 1023) g_rowptr[NN] = run;
}

__global__ void k_fill(const int* __restrict__ e32) {
    int e = blockIdx.x * blockDim.x + threadIdx.x;
    if (e < EE) {
        int d = edge_dst(e32, e);
        int pos = atomicAdd(&g_cursor[d], 1);
        if (pos >= 0 && pos < EE) g_csr[pos] = edge_src(e32, e);
    }
}

// ========== fused: neighbor-mean gather + WMMA GEMM + bias + LN + ReLU =========
// CTA = 128 rows x 128 cols, 512 threads = 16 warps (warp tile 32x32).
// A = [x_fp16 | mean-gathered neigh_fp16] (128 x 256) built in smem;
// B = [Ws | Wn] rows (128 n x 256 k). Single pass: out = A @ B^T, fp32 accum.
#define LDAB 264                              // fp16 elems per row (256 + 8 pad)
#define ABYTES (128 * LDAB * 2)               // 67584
#define SM_BIAS  0
#define SM_GAMMA 512
#define SM_BETA  1024
#define SM_A     2048
#define SM_B     (SM_A + ABYTES)
#define SMEM_TOTAL (SM_B + ABYTES)            // 137216
#define SM_F     SM_A                         // fp32 out stage (stride 132) reuses A
#define LDF      132

__global__ void __launch_bounds__(512, 1)
k_mm(const float* __restrict__ bias,
     const float* __restrict__ gamma,
     const float* __restrict__ beta,
     float* __restrict__ out) {
    extern __shared__ char smem[];
    int tid = threadIdx.x;
    int wid = tid >> 5;

    if (tid < DD) {
        ((float*)(smem + SM_BIAS))[tid] = bias[tid];
        ((float*)(smem + SM_GAMMA))[tid] = gamma[tid];
        ((float*)(smem + SM_BETA))[tid] = beta[tid];
    }

    size_t g0 = (size_t)blockIdx.x * 128;
    int row = tid >> 2;           // 0..127
    int q = tid & 3;              // quarter of a row (64B slice)

    // ---- stage B: 128 rows x 512B (once per CTA) ------------------------------
#pragma unroll
    for (int i = 0; i < 8; i++) {
        int idx = tid + 512 * i;            // 0..4095
        int r = idx >> 5, c = idx & 31;
        *(uint4*)(smem + SM_B + r * (LDAB * 2) + c * 16) = g_w4[idx];
    }

    // ---- stage A part 1: own x fp16 rows (cols 0..127) ------------------------
#pragma unroll
    for (int i = 0; i < 4; i++) {
        int idx = tid + 512 * i;            // 0..2047
        int r = idx >> 4, c = idx & 15;
        *(uint4*)(smem + SM_A + r * (LDAB * 2) + c * 16) = g_xh[(g0 + r) * 16 + c];
    }

    // ---- stage A part 2: gather neighbor mean (cols 128..255) -----------------
    {
        int b = blockIdx.x >> 7;            // 128 tiles per batch
        int n = ((blockIdx.x & 127) << 7) + row;
        int s0 = g_rowptr[n];
        int s1 = g_rowptr[n + 1];
        const uint4* xb = g_xh + (size_t)b * NN * 16 + q * 4;
        float acc[32];
#pragma unroll
        for (int i = 0; i < 32; i++) acc[i] = 0.f;
        for (int e = s0; e < s1; e++) {
            const uint4* p = xb + (size_t)g_csr[e] * 16;
#pragma unroll
            for (int i = 0; i < 4; i++) {
                uint4 u = p[i];
                float2 p0 = __half22float2(*reinterpret_cast<__half2*>(&u.x));
                float2 p1 = __half22float2(*reinterpret_cast<__half2*>(&u.y));
                float2 p2 = __half22float2(*reinterpret_cast<__half2*>(&u.z));
                float2 p3 = __half22float2(*reinterpret_cast<__half2*>(&u.w));
                acc[8 * i + 0] += p0.x; acc[8 * i + 1] += p0.y;
                acc[8 * i + 2] += p1.x; acc[8 * i + 3] += p1.y;
                acc[8 * i + 4] += p2.x; acc[8 * i + 5] += p2.y;
                acc[8 * i + 6] += p3.x; acc[8 * i + 7] += p3.y;
            }
        }
        int d = s1 - s0;
        float inv = 1.0f / (float)(d > 0 ? d : 1);
        uint4* dst = (uint4*)(smem + SM_A + row * (LDAB * 2) + 256 + q * 64);
#pragma unroll
        for (int i = 0; i < 4; i++) {
            dst[i] = make_uint4(packh(acc[8 * i + 0] * inv, acc[8 * i + 1] * inv),
                                packh(acc[8 * i + 2] * inv, acc[8 * i + 3] * inv),
                                packh(acc[8 * i + 4] * inv, acc[8 * i + 5] * inv),
                                packh(acc[8 * i + 6] * inv, acc[8 * i + 7] * inv));
        }
    }
    __syncthreads();

    // ---- single-pass WMMA: 16 kk steps ----------------------------------------
    int wm = wid & 3, wn = wid >> 2;
    int row0 = wm * 32, col0 = wn * 32;

    wmma::fragment<wmma::accumulator, 16, 16, 16, float> fc[2][2];
#pragma unroll
    for (int i = 0; i < 2; i++)
#pragma unroll
        for (int j = 0; j < 2; j++) wmma::fill_fragment(fc[i][j], 0.0f);

    const __half* ab = (const __half*)(smem + SM_A);
    const __half* bb = (const __half*)(smem + SM_B);
#pragma unroll
    for (int kk = 0; kk < 16; kk++) {
        wmma::fragment<wmma::matrix_a, 16, 16, 16, __half, wmma::row_major> fa[2];
        wmma::fragment<wmma::matrix_b, 16, 16, 16, __half, wmma::col_major> fb[2];
        wmma::load_matrix_sync(fa[0], ab + (row0 + 0) * LDAB + kk * 16, LDAB);
        wmma::load_matrix_sync(fa[1], ab + (row0 + 16) * LDAB + kk * 16, LDAB);
        wmma::load_matrix_sync(fb[0], bb + (col0 + 0) * LDAB + kk * 16, LDAB);
        wmma::load_matrix_sync(fb[1], bb + (col0 + 16) * LDAB + kk * 16, LDAB);
#pragma unroll
        for (int i = 0; i < 2; i++)
#pragma unroll
            for (int j = 0; j < 2; j++)
                wmma::mma_sync(fc[i][j], fa[i], fb[j], fc[i][j]);
    }
    __syncthreads();   // done reading A region before overwriting with fp32 stage

    // ---- store accum to smem fp32 ---------------------------------------------
    float* fsm = (float*)(smem + SM_F);
#pragma unroll
    for (int i = 0; i < 2; i++)
#pragma unroll
        for (int j = 0; j < 2; j++)
            wmma::store_matrix_sync(fsm + (row0 + 16 * i) * LDF + col0 + 16 * j,
                                    fc[i][j], LDF, wmma::mem_row_major);
    __syncthreads();

    // ---- bias + LayerNorm + ReLU + store --------------------------------------
    {
        const float* src = fsm + row * LDF + q * 32;
        const float* bs = (const float*)(smem + SM_BIAS) + q * 32;
        float v[32];
        float s = 0.f, ss = 0.f;
#pragma unroll
        for (int c = 0; c < 32; c++) {
            float t = src[c] + bs[c];
            v[c] = t;
            s += t;
            ss += t * t;
        }
        // 4 consecutive lanes share a row: combine quarters
        s  += __shfl_xor_sync(0xFFFFFFFFu, s, 1);
        ss += __shfl_xor_sync(0xFFFFFFFFu, ss, 1);
        s  += __shfl_xor_sync(0xFFFFFFFFu, s, 2);
        ss += __shfl_xor_sync(0xFFFFFFFFu, ss, 2);
        float mean = s * (1.0f / DD);
        float var = ss * (1.0f / DD) - mean * mean;
        float rstd = rsqrtf(var + LN_EPS);
        const float* gs = (const float*)(smem + SM_GAMMA) + q * 32;
        const float* bt = (const float*)(smem + SM_BETA) + q * 32;
        float4* orow = (float4*)(out + (g0 + row) * DD + q * 32);
#pragma unroll
        for (int c4 = 0; c4 < 8; c4++) {
            float v0 = (v[4 * c4 + 0] - mean) * rstd * gs[4 * c4 + 0] + bt[4 * c4 + 0];
            float v1 = (v[4 * c4 + 1] - mean) * rstd * gs[4 * c4 + 1] + bt[4 * c4 + 1];
            float v2 = (v[4 * c4 + 2] - mean) * rstd * gs[4 * c4 + 2] + bt[4 * c4 + 2];
            float v3 = (v[4 * c4 + 3] - mean) * rstd * gs[4 * c4 + 3] + bt[4 * c4 + 3];
            float4 ov;
            ov.x = v0 > 0.f ? v0 : 0.f;
            ov.y = v1 > 0.f ? v1 : 0.f;
            ov.z = v2 > 0.f ? v2 : 0.f;
            ov.w = v3 > 0.f ? v3 : 0.f;
            orow[c4] = ov;
        }
    }
}

// ================= launch ======================================================
extern "C" void kernel_launch(void* const* d_in, const int* in_sizes, int n_in,
                              void* d_out, int out_size) {
    const float* x = nullptr;
    const int* edge = nullptr;
    const float* Wself = nullptr;
    const float* Wneigh = nullptr;
    const float* bias = nullptr;
    const float* gamma = nullptr;
    const float* beta = nullptr;
    int nW = 0, nV = 0;
    for (int i = 0; i < n_in; i++) {
        int s = in_sizes[i];
        if (s == NODES * DD) {
            if (!x) x = (const float*)d_in[i];
        } else if (s == 2 * EE || s == 4 * EE) {
            edge = (const int*)d_in[i];
        } else if (s == DD * DD) {
            if (nW == 0) Wself = (const float*)d_in[i];
            else if (nW == 1) Wneigh = (const float*)d_in[i];
            nW++;
        } else if (s == DD) {
            if (nV == 0) bias = (const float*)d_in[i];
            else if (nV == 1) gamma = (const float*)d_in[i];
            else if (nV == 2) beta = (const float*)d_in[i];
            nV++;
        }
    }

    cudaFuncSetAttribute(k_mm, cudaFuncAttributeMaxDynamicSharedMemorySize, SMEM_TOTAL);

    k_init<<<EE / 256, 256>>>(edge, Wself, Wneigh);
    k_count_xh<<<NODES * 16 / 256, 256>>>(edge, x);
    k_scan<<<1, 1024>>>();
    k_fill<<<EE / 256, 256>>>(edge);
    k_mm<<<NODES / 128, 512, SMEM_TOTAL>>>(bias, gamma, beta, (float*)d_out);
}